// round 10
// baseline (speedup 1.0000x reference)
#include <cuda_runtime.h>

#define NBLK 128                // threads per block
#define SPB  112                // samples per block (smem-sized for 4 blocks/SM)
#define NJ   21
#define FPT  63                 // floats per sample (21 joints x 3)
#define TILE (SPB * FPT)        // 7056 floats per array per block
#define SMEM_BYTES (2 * TILE * (int)sizeof(float))   // 56448 B

struct V3 { float x, y, z; };

__device__ __forceinline__ V3 mkv3(float x, float y, float z) { V3 r; r.x = x; r.y = y; r.z = z; return r; }
__device__ __forceinline__ V3 sub3(V3 a, V3 b) { return mkv3(a.x - b.x, a.y - b.y, a.z - b.z); }
__device__ __forceinline__ V3 add3(V3 a, V3 b) { return mkv3(a.x + b.x, a.y + b.y, a.z + b.z); }
__device__ __forceinline__ V3 scl3(V3 a, float s) { return mkv3(a.x * s, a.y * s, a.z * s); }
__device__ __forceinline__ float dot3(V3 a, V3 b) { return a.x * b.x + a.y * b.y + a.z * b.z; }
__device__ __forceinline__ V3 cross3(V3 a, V3 b) {
    return mkv3(a.y * b.z - a.z * b.y, a.z * b.x - a.x * b.z, a.x * b.y - a.y * b.x);
}

// Rodrigues rotation taking v0 toward v1 (reference _rot_between semantics).
struct Rot { float ax, ay, az, s, omc; };

__device__ __forceinline__ Rot makeRot(V3 v0, V3 v1) {
    float i0 = rsqrtf(fmaxf(dot3(v0, v0), 1e-30f));
    float i1 = rsqrtf(fmaxf(dot3(v1, v1), 1e-30f));
    V3 n0 = scl3(v0, i0);
    V3 n1 = scl3(v1, i1);
    float c = dot3(n0, n1);
    V3 ax = cross3(n0, n1);
    float s2 = dot3(ax, ax);
    float is = rsqrtf(fmaxf(s2, 1e-30f));
    float s = s2 * is;           // = sqrt(s2), 0 when s2 == 0
    Rot r;
    r.ax = ax.x * is; r.ay = ax.y * is; r.az = ax.z * is;
    r.s = s; r.omc = 1.0f - c;
    return r;
}

// R w = w + s (k x w) + (1-c) (k x (k x w))
__device__ __forceinline__ V3 rotApply(const Rot& r, V3 w) {
    V3 a = mkv3(r.ax, r.ay, r.az);
    V3 k1 = cross3(a, w);
    V3 k2 = cross3(a, k1);
    return mkv3(w.x + r.s * k1.x + r.omc * k2.x,
                w.y + r.s * k1.y + r.omc * k2.y,
                w.z + r.s * k1.z + r.omc * k2.z);
}

// Branchless division-free exact Jacobi rotation on symmetric 4x4 (pair P,Q).
#define JROT(app, aqq, apq, arp1, arq1, arp2, arq2, v0p, v0q, v1p, v1q, v2p, v2q, v3p, v3q) \
do {                                                                                        \
    float _apq = apq;                                                                       \
    float _t2  = 2.0f * _apq;                                                               \
    float _d   = aqq - app;                                                                 \
    float _invr = rsqrtf(fmaxf(_t2 * _t2 + _d * _d, 1e-38f));                               \
    float _co  = fabsf(_d) * _invr;                                                         \
    float _c2v = 0.5f * (1.0f + _co);                                                       \
    float _ir2 = rsqrtf(_c2v);                                                              \
    float _cc  = _c2v * _ir2;                                                               \
    float _sg  = (_d >= 0.0f) ? 0.5f : -0.5f;                                               \
    float _ss  = _sg * _t2 * _invr * _ir2;                                                  \
    float _tt  = _ss * _ir2;                                                                \
    app = app - _tt * _apq;                                                                 \
    aqq = aqq + _tt * _apq;                                                                 \
    apq = 0.0f;                                                                             \
    float _t1x, _t2x;                                                                       \
    _t1x = arp1; _t2x = arq1; arp1 = _cc*_t1x - _ss*_t2x; arq1 = _ss*_t1x + _cc*_t2x;       \
    _t1x = arp2; _t2x = arq2; arp2 = _cc*_t1x - _ss*_t2x; arq2 = _ss*_t1x + _cc*_t2x;       \
    _t1x = v0p;  _t2x = v0q;  v0p  = _cc*_t1x - _ss*_t2x; v0q  = _ss*_t1x + _cc*_t2x;       \
    _t1x = v1p;  _t2x = v1q;  v1p  = _cc*_t1x - _ss*_t2x; v1q  = _ss*_t1x + _cc*_t2x;       \
    _t1x = v2p;  _t2x = v2q;  v2p  = _cc*_t1x - _ss*_t2x; v2q  = _ss*_t1x + _cc*_t2x;       \
    _t1x = v3p;  _t2x = v3q;  v3p  = _cc*_t1x - _ss*_t2x; v3q  = _ss*_t1x + _cc*_t2x;       \
} while (0)

__global__ void __launch_bounds__(NBLK, 4)
kin_kernel(const float* __restrict__ jgt, const float* __restrict__ tpl,
           float* __restrict__ out, int n)
{
    extern __shared__ float smem_dyn[];
    float* sG = smem_dyn;          // joint_gt tile
    float* sT = smem_dyn + TILE;   // tempJ tile; reused as output tile

    const int tid = threadIdx.x;
    const long long base = (long long)blockIdx.x * TILE;
    const long long nF = (long long)n * FPT;
    const bool full = (base + TILE) <= nF;

    // ---- coalesced staging: gmem -> smem (all 128 threads) ----
    if (full) {
        const float4* g4 = reinterpret_cast<const float4*>(jgt + base);
        const float4* t4 = reinterpret_cast<const float4*>(tpl + base);
        float4* sG4 = reinterpret_cast<float4*>(sG);
        float4* sT4 = reinterpret_cast<float4*>(sT);
        for (int k = tid; k < TILE / 4; k += NBLK) { sG4[k] = g4[k]; sT4[k] = t4[k]; }
    } else {
        for (int k = tid; k < TILE; k += NBLK) {
            long long gi = base + k;
            if (gi < nF) { sG[k] = jgt[gi]; sT[k] = tpl[gi]; }
        }
    }
    __syncthreads();

    const int samp = blockIdx.x * SPB + tid;
    if (tid < SPB && samp < n) {
        const int bt = tid * FPT;
        const V3 wg = mkv3(sG[bt + 0], sG[bt + 1], sG[bt + 2]);  // joint_gt wrist
        const V3 wt = mkv3(sT[bt + 0], sT[bt + 1], sT[bt + 2]);  // tempJ wrist

        // ---- H = sum_j tJ0_j * jg_j^T (j=0 term is exactly zero) ----
        float h00 = 0.f, h01 = 0.f, h02 = 0.f;
        float h10 = 0.f, h11 = 0.f, h12 = 0.f;
        float h20 = 0.f, h21 = 0.f, h22 = 0.f;
        #pragma unroll 5
        for (int j = 1; j < NJ; ++j) {
            float ax = sT[bt + 3 * j + 0] - wt.x;
            float ay = sT[bt + 3 * j + 1] - wt.y;
            float az = sT[bt + 3 * j + 2] - wt.z;
            float bx = sG[bt + 3 * j + 0] - wg.x;
            float by = sG[bt + 3 * j + 1] - wg.y;
            float bz = sG[bt + 3 * j + 2] - wg.z;
            h00 += ax * bx; h01 += ax * by; h02 += ax * bz;
            h10 += ay * bx; h11 += ay * by; h12 += ay * bz;
            h20 += az * bx; h21 += az * by; h22 += az * bz;
        }

        // ---- Horn 4x4 matrix; max eigenvector = quaternion of Kabsch R ----
        float A00 = h00 + h11 + h22;
        float A01 = h12 - h21;
        float A02 = h20 - h02;
        float A03 = h01 - h10;
        float A11 = h00 - h11 - h22;
        float A12 = h01 + h10;
        float A13 = h02 + h20;
        float A22 = -h00 + h11 - h22;
        float A23 = h12 + h21;
        float A33 = -h00 - h11 + h22;

        float V00 = 1.f, V01 = 0.f, V02 = 0.f, V03 = 0.f;
        float V10 = 0.f, V11 = 1.f, V12 = 0.f, V13 = 0.f;
        float V20 = 0.f, V21 = 0.f, V22 = 1.f, V23 = 0.f;
        float V30 = 0.f, V31 = 0.f, V32 = 0.f, V33 = 1.f;

        // Brent-Luk paired ordering: 3 stages of disjoint pairs per sweep.
        #pragma unroll
        for (int sweep = 0; sweep < 4; ++sweep) {
            // stage 1: (0,1) || (2,3)
            JROT(A00, A11, A01, A02, A12, A03, A13, V00, V01, V10, V11, V20, V21, V30, V31);
            JROT(A22, A33, A23, A02, A03, A12, A13, V02, V03, V12, V13, V22, V23, V32, V33);
            // stage 2: (0,2) || (1,3)
            JROT(A00, A22, A02, A01, A12, A03, A23, V00, V02, V10, V12, V20, V22, V30, V32);
            JROT(A11, A33, A13, A01, A03, A12, A23, V01, V03, V11, V13, V21, V23, V31, V33);
            // stage 3: (0,3) || (1,2)
            JROT(A00, A33, A03, A01, A13, A02, A23, V00, V03, V10, V13, V20, V23, V30, V33);
            JROT(A11, A22, A12, A01, A02, A13, A23, V01, V02, V11, V12, V21, V22, V31, V32);
        }

        float qw = V00, qx = V10, qy = V20, qz = V30, bd = A00;
        if (A11 > bd) { bd = A11; qw = V01; qx = V11; qy = V21; qz = V31; }
        if (A22 > bd) { bd = A22; qw = V02; qx = V12; qy = V22; qz = V32; }
        if (A33 > bd) { bd = A33; qw = V03; qx = V13; qy = V23; qz = V33; }
        float qn = rsqrtf(qw * qw + qx * qx + qy * qy + qz * qz);
        qw *= qn; qx *= qn; qy *= qn; qz *= qn;

        const float r00 = 1.f - 2.f * (qy * qy + qz * qz);
        const float r01 = 2.f * (qx * qy - qw * qz);
        const float r02 = 2.f * (qx * qz + qw * qy);
        const float r10 = 2.f * (qx * qy + qw * qz);
        const float r11 = 1.f - 2.f * (qx * qx + qz * qz);
        const float r12 = 2.f * (qy * qz - qw * qx);
        const float r20 = 2.f * (qx * qz - qw * qy);
        const float r21 = 2.f * (qy * qz + qw * qx);
        const float r22 = 1.f - 2.f * (qx * qx + qy * qy);

        // output joint 0 = wrist of joint_gt
        sT[bt + 0] = wg.x; sT[bt + 1] = wg.y; sT[bt + 2] = wg.z;

        // ---- per-finger chain: bones rotate descendants in place; final tJ == pos ----
        const int tipIdx[5] = {17, 18, 20, 19, 16};
        #pragma unroll
        for (int f = 0; f < 5; ++f) {
            const int a = 3 * f + 1;
            const int jidx[4] = {a, a + 1, a + 2, tipIdx[f]};
            V3 P[4], G[3];
            #pragma unroll
            for (int k = 0; k < 4; ++k) {
                const int j = jidx[k];
                float tx = sT[bt + 3 * j + 0] - wt.x;
                float ty = sT[bt + 3 * j + 1] - wt.y;
                float tz = sT[bt + 3 * j + 2] - wt.z;
                P[k] = mkv3(r00 * tx + r01 * ty + r02 * tz,
                            r10 * tx + r11 * ty + r12 * tz,
                            r20 * tx + r21 * ty + r22 * tz);
            }
            #pragma unroll
            for (int k = 0; k < 3; ++k) {
                const int j = jidx[k + 1];
                G[k] = mkv3(sG[bt + 3 * j + 0] - wg.x,
                            sG[bt + 3 * j + 1] - wg.y,
                            sG[bt + 3 * j + 2] - wg.z);
            }
            {   // bone 1: pivot a, child a+1; rotate {a+1, a+2, tip}
                Rot r = makeRot(sub3(P[1], P[0]), sub3(G[0], P[0]));
                P[1] = add3(rotApply(r, sub3(P[1], P[0])), P[0]);
                P[2] = add3(rotApply(r, sub3(P[2], P[0])), P[0]);
                P[3] = add3(rotApply(r, sub3(P[3], P[0])), P[0]);
            }
            {   // bone 2: pivot a+1, child a+2; rotate {a+2, tip}
                Rot r = makeRot(sub3(P[2], P[1]), sub3(G[1], P[1]));
                P[2] = add3(rotApply(r, sub3(P[2], P[1])), P[1]);
                P[3] = add3(rotApply(r, sub3(P[3], P[1])), P[1]);
            }
            {   // bone 3: pivot a+2, child tip; rotate {tip}
                Rot r = makeRot(sub3(P[3], P[2]), sub3(G[2], P[2]));
                P[3] = add3(rotApply(r, sub3(P[3], P[2])), P[2]);
            }
            #pragma unroll
            for (int k = 0; k < 4; ++k) {
                const int j = jidx[k];
                sT[bt + 3 * j + 0] = P[k].x + wg.x;
                sT[bt + 3 * j + 1] = P[k].y + wg.y;
                sT[bt + 3 * j + 2] = P[k].z + wg.z;
            }
        }
    }
    __syncthreads();

    // ---- coalesced store: smem -> gmem (all 128 threads) ----
    if (full) {
        float4* o4 = reinterpret_cast<float4*>(out + base);
        const float4* sT4 = reinterpret_cast<const float4*>(sT);
        for (int k = tid; k < TILE / 4; k += NBLK) o4[k] = sT4[k];
    } else {
        for (int k = tid; k < TILE; k += NBLK) {
            long long gi = base + k;
            if (gi < nF) out[gi] = sT[k];
        }
    }
}

extern "C" void kernel_launch(void* const* d_in, const int* in_sizes, int n_in,
                              void* d_out, int out_size) {
    const float* jgt = (const float*)d_in[0];   // joint_gt [N,21,3]
    const float* tpl = (const float*)d_in[1];   // tempJ    [N,21,3]
    float* out = (float*)d_out;                 // [N,21,3] float32
    (void)n_in; (void)out_size;

    static bool attr_set = false;               // idempotent attribute config
    if (!attr_set) {
        cudaFuncSetAttribute(kin_kernel, cudaFuncAttributeMaxDynamicSharedMemorySize, SMEM_BYTES);
        attr_set = true;
    }

    const int n = in_sizes[0] / FPT;
    const int blocks = (n + SPB - 1) / SPB;
    kin_kernel<<<blocks, NBLK, SMEM_BYTES>>>(jgt, tpl, out, n);
}

// round 11
// speedup vs baseline: 1.3029x; 1.3029x over previous
#include <cuda_runtime.h>

#define NBLK 128
#define NJ   21
#define FPT  63                 // floats per sample (21 joints x 3)
#define TILE (NBLK * FPT)       // 8064 floats per array per block
#define SMEM_BYTES (2 * TILE * (int)sizeof(float))   // 64512 B

struct V3 { float x, y, z; };

__device__ __forceinline__ V3 mkv3(float x, float y, float z) { V3 r; r.x = x; r.y = y; r.z = z; return r; }
__device__ __forceinline__ V3 sub3(V3 a, V3 b) { return mkv3(a.x - b.x, a.y - b.y, a.z - b.z); }
__device__ __forceinline__ V3 add3(V3 a, V3 b) { return mkv3(a.x + b.x, a.y + b.y, a.z + b.z); }
__device__ __forceinline__ V3 scl3(V3 a, float s) { return mkv3(a.x * s, a.y * s, a.z * s); }
__device__ __forceinline__ float dot3(V3 a, V3 b) { return a.x * b.x + a.y * b.y + a.z * b.z; }
__device__ __forceinline__ V3 cross3(V3 a, V3 b) {
    return mkv3(a.y * b.z - a.z * b.y, a.z * b.x - a.x * b.z, a.x * b.y - a.y * b.x);
}

// Branchless division-free exact Jacobi rotation on symmetric 4x4 (pair P,Q).
#define JROT(app, aqq, apq, arp1, arq1, arp2, arq2, v0p, v0q, v1p, v1q, v2p, v2q, v3p, v3q) \
do {                                                                                        \
    float _apq = apq;                                                                       \
    float _t2  = 2.0f * _apq;                                                               \
    float _d   = aqq - app;                                                                 \
    float _invr = rsqrtf(fmaxf(_t2 * _t2 + _d * _d, 1e-38f));                               \
    float _co  = fabsf(_d) * _invr;                                                         \
    float _c2v = 0.5f * (1.0f + _co);                                                       \
    float _ir2 = rsqrtf(_c2v);                                                              \
    float _cc  = _c2v * _ir2;                                                               \
    float _sg  = (_d >= 0.0f) ? 0.5f : -0.5f;                                               \
    float _ss  = _sg * _t2 * _invr * _ir2;                                                  \
    float _tt  = _ss * _ir2;                                                                \
    app = app - _tt * _apq;                                                                 \
    aqq = aqq + _tt * _apq;                                                                 \
    apq = 0.0f;                                                                             \
    float _t1x, _t2x;                                                                       \
    _t1x = arp1; _t2x = arq1; arp1 = _cc*_t1x - _ss*_t2x; arq1 = _ss*_t1x + _cc*_t2x;       \
    _t1x = arp2; _t2x = arq2; arp2 = _cc*_t1x - _ss*_t2x; arq2 = _ss*_t1x + _cc*_t2x;       \
    _t1x = v0p;  _t2x = v0q;  v0p  = _cc*_t1x - _ss*_t2x; v0q  = _ss*_t1x + _cc*_t2x;       \
    _t1x = v1p;  _t2x = v1q;  v1p  = _cc*_t1x - _ss*_t2x; v1q  = _ss*_t1x + _cc*_t2x;       \
    _t1x = v2p;  _t2x = v2q;  v2p  = _cc*_t1x - _ss*_t2x; v2q  = _ss*_t1x + _cc*_t2x;       \
    _t1x = v3p;  _t2x = v3q;  v3p  = _cc*_t1x - _ss*_t2x; v3q  = _ss*_t1x + _cc*_t2x;       \
} while (0)

__global__ void __launch_bounds__(NBLK, 3)
kin_kernel(const float* __restrict__ jgt, const float* __restrict__ tpl,
           float* __restrict__ out, int n)
{
    extern __shared__ float smem_dyn[];
    float* sG = smem_dyn;          // joint_gt tile
    float* sT = smem_dyn + TILE;   // tempJ tile; reused as output tile

    const int tid = threadIdx.x;
    const long long base = (long long)blockIdx.x * TILE;
    const long long nF = (long long)n * FPT;
    const bool full = (base + TILE) <= nF;

    // ---- coalesced staging: gmem -> smem ----
    if (full) {
        const float4* g4 = reinterpret_cast<const float4*>(jgt + base);
        const float4* t4 = reinterpret_cast<const float4*>(tpl + base);
        float4* sG4 = reinterpret_cast<float4*>(sG);
        float4* sT4 = reinterpret_cast<float4*>(sT);
        #pragma unroll 4
        for (int k = tid; k < TILE / 4; k += NBLK) { sG4[k] = g4[k]; sT4[k] = t4[k]; }
    } else {
        for (int k = tid; k < TILE; k += NBLK) {
            long long gi = base + k;
            if (gi < nF) { sG[k] = jgt[gi]; sT[k] = tpl[gi]; }
        }
    }
    __syncthreads();

    const int samp = blockIdx.x * NBLK + tid;
    if (samp < n) {
        const int bt = tid * FPT;
        const V3 wg = mkv3(sG[bt + 0], sG[bt + 1], sG[bt + 2]);  // joint_gt wrist
        const V3 wt = mkv3(sT[bt + 0], sT[bt + 1], sT[bt + 2]);  // tempJ wrist

        // ---- H = sum_j tJ0_j * jg_j^T (j=0 term is exactly zero) ----
        float h00 = 0.f, h01 = 0.f, h02 = 0.f;
        float h10 = 0.f, h11 = 0.f, h12 = 0.f;
        float h20 = 0.f, h21 = 0.f, h22 = 0.f;
        #pragma unroll
        for (int j = 1; j < NJ; ++j) {
            float ax = sT[bt + 3 * j + 0] - wt.x;
            float ay = sT[bt + 3 * j + 1] - wt.y;
            float az = sT[bt + 3 * j + 2] - wt.z;
            float bx = sG[bt + 3 * j + 0] - wg.x;
            float by = sG[bt + 3 * j + 1] - wg.y;
            float bz = sG[bt + 3 * j + 2] - wg.z;
            h00 += ax * bx; h01 += ax * by; h02 += ax * bz;
            h10 += ay * bx; h11 += ay * by; h12 += ay * bz;
            h20 += az * bx; h21 += az * by; h22 += az * bz;
        }

        // ---- Horn 4x4 matrix; max eigenvector = quaternion of Kabsch R ----
        float A00 = h00 + h11 + h22;
        float A01 = h12 - h21;
        float A02 = h20 - h02;
        float A03 = h01 - h10;
        float A11 = h00 - h11 - h22;
        float A12 = h01 + h10;
        float A13 = h02 + h20;
        float A22 = -h00 + h11 - h22;
        float A23 = h12 + h21;
        float A33 = -h00 - h11 + h22;

        float V00 = 1.f, V01 = 0.f, V02 = 0.f, V03 = 0.f;
        float V10 = 0.f, V11 = 1.f, V12 = 0.f, V13 = 0.f;
        float V20 = 0.f, V21 = 0.f, V22 = 1.f, V23 = 0.f;
        float V30 = 0.f, V31 = 0.f, V32 = 0.f, V33 = 1.f;

        // Brent-Luk paired ordering: 3 stages of disjoint pairs per sweep.
        #pragma unroll
        for (int sweep = 0; sweep < 4; ++sweep) {
            // stage 1: (0,1) || (2,3)
            JROT(A00, A11, A01, A02, A12, A03, A13, V00, V01, V10, V11, V20, V21, V30, V31);
            JROT(A22, A33, A23, A02, A03, A12, A13, V02, V03, V12, V13, V22, V23, V32, V33);
            // stage 2: (0,2) || (1,3)
            JROT(A00, A22, A02, A01, A12, A03, A23, V00, V02, V10, V12, V20, V22, V30, V32);
            JROT(A11, A33, A13, A01, A03, A12, A23, V01, V03, V11, V13, V21, V23, V31, V33);
            // stage 3: (0,3) || (1,2)
            JROT(A00, A33, A03, A01, A13, A02, A23, V00, V03, V10, V13, V20, V23, V30, V33);
            JROT(A11, A22, A12, A01, A02, A13, A23, V01, V02, V11, V12, V21, V22, V31, V32);
        }

        float qw = V00, qx = V10, qy = V20, qz = V30, bd = A00;
        if (A11 > bd) { bd = A11; qw = V01; qx = V11; qy = V21; qz = V31; }
        if (A22 > bd) { bd = A22; qw = V02; qx = V12; qy = V22; qz = V32; }
        if (A33 > bd) { bd = A33; qw = V03; qx = V13; qy = V23; qz = V33; }
        float qn = rsqrtf(qw * qw + qx * qx + qy * qy + qz * qz);
        qw *= qn; qx *= qn; qy *= qn; qz *= qn;

        const float r00 = 1.f - 2.f * (qy * qy + qz * qz);
        const float r01 = 2.f * (qx * qy - qw * qz);
        const float r02 = 2.f * (qx * qz + qw * qy);
        const float r10 = 2.f * (qx * qy + qw * qz);
        const float r11 = 1.f - 2.f * (qx * qx + qz * qz);
        const float r12 = 2.f * (qy * qz - qw * qx);
        const float r20 = 2.f * (qx * qz - qw * qy);
        const float r21 = 2.f * (qy * qz + qw * qx);
        const float r22 = 1.f - 2.f * (qx * qx + qy * qy);

        // output joint 0 = wrist of joint_gt
        sT[bt + 0] = wg.x; sT[bt + 1] = wg.y; sT[bt + 2] = wg.z;

        // ---- per-finger chain. Bone rotation identities used:
        //   (1) R(n0->n1) maps v0 exactly to |v0|*n1  -> direct child needs no rotApply
        //   (2) with a = n0 x n1 (unnormalized), R w = w + a x w + (a x (a x w))/(1+c)
        //       since (1-c)/s^2 = 1/(1+c). No axis normalization needed.
        const int tipIdx[5] = {17, 18, 20, 19, 16};
        #pragma unroll
        for (int f = 0; f < 5; ++f) {
            const int a0 = 3 * f + 1;
            const int jidx[4] = {a0, a0 + 1, a0 + 2, tipIdx[f]};
            V3 P[4], G[3];
            #pragma unroll
            for (int k = 0; k < 4; ++k) {
                const int j = jidx[k];
                float tx = sT[bt + 3 * j + 0] - wt.x;
                float ty = sT[bt + 3 * j + 1] - wt.y;
                float tz = sT[bt + 3 * j + 2] - wt.z;
                P[k] = mkv3(r00 * tx + r01 * ty + r02 * tz,
                            r10 * tx + r11 * ty + r12 * tz,
                            r20 * tx + r21 * ty + r22 * tz);
            }
            #pragma unroll
            for (int k = 0; k < 3; ++k) {
                const int j = jidx[k + 1];
                G[k] = mkv3(sG[bt + 3 * j + 0] - wg.x,
                            sG[bt + 3 * j + 1] - wg.y,
                            sG[bt + 3 * j + 2] - wg.z);
            }
            {   // bone 1: pivot P0; direct child P1; rotate P2, P3
                V3 v0 = sub3(P[1], P[0]);
                V3 v1 = sub3(G[0], P[0]);
                float d0 = dot3(v0, v0), d1 = dot3(v1, v1);
                float i0 = rsqrtf(fmaxf(d0, 1e-30f));
                float i1 = rsqrtf(fmaxf(d1, 1e-30f));
                V3 n0 = scl3(v0, i0), n1 = scl3(v1, i1);
                float c = dot3(n0, n1);
                V3 ax = cross3(n0, n1);
                float fct = __fdividef(1.0f, fmaxf(1.0f + c, 1e-12f));
                P[1] = add3(P[0], scl3(n1, d0 * i0));
                V3 w2 = sub3(P[2], P[0]);
                V3 aw2 = cross3(ax, w2); V3 aaw2 = cross3(ax, aw2);
                P[2] = add3(P[0], add3(w2, add3(aw2, scl3(aaw2, fct))));
                V3 w3 = sub3(P[3], P[0]);
                V3 aw3 = cross3(ax, w3); V3 aaw3 = cross3(ax, aw3);
                P[3] = add3(P[0], add3(w3, add3(aw3, scl3(aaw3, fct))));
            }
            {   // bone 2: pivot P1; direct child P2; rotate P3
                V3 v0 = sub3(P[2], P[1]);
                V3 v1 = sub3(G[1], P[1]);
                float d0 = dot3(v0, v0), d1 = dot3(v1, v1);
                float i0 = rsqrtf(fmaxf(d0, 1e-30f));
                float i1 = rsqrtf(fmaxf(d1, 1e-30f));
                V3 n0 = scl3(v0, i0), n1 = scl3(v1, i1);
                float c = dot3(n0, n1);
                V3 ax = cross3(n0, n1);
                float fct = __fdividef(1.0f, fmaxf(1.0f + c, 1e-12f));
                P[2] = add3(P[1], scl3(n1, d0 * i0));
                V3 w3 = sub3(P[3], P[1]);
                V3 aw3 = cross3(ax, w3); V3 aaw3 = cross3(ax, aw3);
                P[3] = add3(P[1], add3(w3, add3(aw3, scl3(aaw3, fct))));
            }
            {   // bone 3: pivot P2; direct child P3 only -> pure length transfer
                V3 v0 = sub3(P[3], P[2]);
                V3 v1 = sub3(G[2], P[2]);
                float d0 = dot3(v0, v0), d1 = dot3(v1, v1);
                float i0 = rsqrtf(fmaxf(d0, 1e-30f));
                float i1 = rsqrtf(fmaxf(d1, 1e-30f));
                P[3] = add3(P[2], scl3(v1, d0 * i0 * i1));
            }
            #pragma unroll
            for (int k = 0; k < 4; ++k) {
                const int j = jidx[k];
                sT[bt + 3 * j + 0] = P[k].x + wg.x;
                sT[bt + 3 * j + 1] = P[k].y + wg.y;
                sT[bt + 3 * j + 2] = P[k].z + wg.z;
            }
        }
    }
    __syncthreads();

    // ---- coalesced store: smem -> gmem ----
    if (full) {
        float4* o4 = reinterpret_cast<float4*>(out + base);
        const float4* sT4 = reinterpret_cast<const float4*>(sT);
        #pragma unroll 4
        for (int k = tid; k < TILE / 4; k += NBLK) o4[k] = sT4[k];
    } else {
        for (int k = tid; k < TILE; k += NBLK) {
            long long gi = base + k;
            if (gi < nF) out[gi] = sT[k];
        }
    }
}

extern "C" void kernel_launch(void* const* d_in, const int* in_sizes, int n_in,
                              void* d_out, int out_size) {
    const float* jgt = (const float*)d_in[0];   // joint_gt [N,21,3]
    const float* tpl = (const float*)d_in[1];   // tempJ    [N,21,3]
    float* out = (float*)d_out;                 // [N,21,3] float32
    (void)n_in; (void)out_size;

    static bool attr_set = false;               // idempotent attribute config
    if (!attr_set) {
        cudaFuncSetAttribute(kin_kernel, cudaFuncAttributeMaxDynamicSharedMemorySize, SMEM_BYTES);
        attr_set = true;
    }

    const int n = in_sizes[0] / FPT;
    const int blocks = (n + NBLK - 1) / NBLK;
    kin_kernel<<<blocks, NBLK, SMEM_BYTES>>>(jgt, tpl, out, n);
}

// round 14
// speedup vs baseline: 1.3556x; 1.0404x over previous
#include <cuda_runtime.h>

#define NBLK 128
#define NJ   21
#define FPT  63                 // floats per sample (21 joints x 3)
#define TILE (NBLK * FPT)       // 8064 floats per array per block
#define SMEM_BYTES (2 * TILE * (int)sizeof(float))   // 64512 B

struct V3 { float x, y, z; };

__device__ __forceinline__ V3 mkv3(float x, float y, float z) { V3 r; r.x = x; r.y = y; r.z = z; return r; }
__device__ __forceinline__ V3 sub3(V3 a, V3 b) { return mkv3(a.x - b.x, a.y - b.y, a.z - b.z); }
__device__ __forceinline__ V3 add3(V3 a, V3 b) { return mkv3(a.x + b.x, a.y + b.y, a.z + b.z); }
__device__ __forceinline__ V3 scl3(V3 a, float s) { return mkv3(a.x * s, a.y * s, a.z * s); }
__device__ __forceinline__ float dot3(V3 a, V3 b) { return a.x * b.x + a.y * b.y + a.z * b.z; }
__device__ __forceinline__ V3 cross3(V3 a, V3 b) {
    return mkv3(a.y * b.z - a.z * b.y, a.z * b.x - a.x * b.z, a.x * b.y - a.y * b.x);
}

// Branchless division-free exact Jacobi rotation on symmetric 4x4 (pair P,Q).
#define JROT(app, aqq, apq, arp1, arq1, arp2, arq2, v0p, v0q, v1p, v1q, v2p, v2q, v3p, v3q) \
do {                                                                                        \
    float _apq = apq;                                                                       \
    float _t2  = 2.0f * _apq;                                                               \
    float _d   = aqq - app;                                                                 \
    float _invr = rsqrtf(fmaxf(_t2 * _t2 + _d * _d, 1e-38f));                               \
    float _co  = fabsf(_d) * _invr;                                                         \
    float _c2v = 0.5f * (1.0f + _co);                                                       \
    float _ir2 = rsqrtf(_c2v);                                                              \
    float _cc  = _c2v * _ir2;                                                               \
    float _sg  = (_d >= 0.0f) ? 0.5f : -0.5f;                                               \
    float _ss  = _sg * _t2 * _invr * _ir2;                                                  \
    float _tt  = _ss * _ir2;                                                                \
    app = app - _tt * _apq;                                                                 \
    aqq = aqq + _tt * _apq;                                                                 \
    apq = 0.0f;                                                                             \
    float _t1x, _t2x;                                                                       \
    _t1x = arp1; _t2x = arq1; arp1 = _cc*_t1x - _ss*_t2x; arq1 = _ss*_t1x + _cc*_t2x;       \
    _t1x = arp2; _t2x = arq2; arp2 = _cc*_t1x - _ss*_t2x; arq2 = _ss*_t1x + _cc*_t2x;       \
    _t1x = v0p;  _t2x = v0q;  v0p  = _cc*_t1x - _ss*_t2x; v0q  = _ss*_t1x + _cc*_t2x;       \
    _t1x = v1p;  _t2x = v1q;  v1p  = _cc*_t1x - _ss*_t2x; v1q  = _ss*_t1x + _cc*_t2x;       \
    _t1x = v2p;  _t2x = v2q;  v2p  = _cc*_t1x - _ss*_t2x; v2q  = _ss*_t1x + _cc*_t2x;       \
    _t1x = v3p;  _t2x = v3q;  v3p  = _cc*_t1x - _ss*_t2x; v3q  = _ss*_t1x + _cc*_t2x;       \
} while (0)

__global__ void __launch_bounds__(NBLK, 3)
kin_kernel(const float* __restrict__ jgt, const float* __restrict__ tpl,
           float* __restrict__ out, int n)
{
    extern __shared__ float smem_dyn[];
    float* sG = smem_dyn;          // joint_gt tile
    float* sT = smem_dyn + TILE;   // tempJ tile; reused as output tile

    const int tid = threadIdx.x;
    const long long base = (long long)blockIdx.x * TILE;
    const long long nF = (long long)n * FPT;
    const bool full = (base + TILE) <= nF;

    // ---- coalesced staging: gmem -> smem ----
    if (full) {
        const float4* g4 = reinterpret_cast<const float4*>(jgt + base);
        const float4* t4 = reinterpret_cast<const float4*>(tpl + base);
        float4* sG4 = reinterpret_cast<float4*>(sG);
        float4* sT4 = reinterpret_cast<float4*>(sT);
        #pragma unroll 4
        for (int k = tid; k < TILE / 4; k += NBLK) { sG4[k] = g4[k]; sT4[k] = t4[k]; }
    } else {
        for (int k = tid; k < TILE; k += NBLK) {
            long long gi = base + k;
            if (gi < nF) { sG[k] = jgt[gi]; sT[k] = tpl[gi]; }
        }
    }
    __syncthreads();

    const int samp = blockIdx.x * NBLK + tid;
    if (samp < n) {
        const int bt = tid * FPT;
        const V3 wg = mkv3(sG[bt + 0], sG[bt + 1], sG[bt + 2]);  // joint_gt wrist
        const V3 wt = mkv3(sT[bt + 0], sT[bt + 1], sT[bt + 2]);  // tempJ wrist

        // ---- H = sum_j tJ0_j * jg_j^T (j=0 term is exactly zero) ----
        float h00 = 0.f, h01 = 0.f, h02 = 0.f;
        float h10 = 0.f, h11 = 0.f, h12 = 0.f;
        float h20 = 0.f, h21 = 0.f, h22 = 0.f;
        #pragma unroll
        for (int j = 1; j < NJ; ++j) {
            float ax = sT[bt + 3 * j + 0] - wt.x;
            float ay = sT[bt + 3 * j + 1] - wt.y;
            float az = sT[bt + 3 * j + 2] - wt.z;
            float bx = sG[bt + 3 * j + 0] - wg.x;
            float by = sG[bt + 3 * j + 1] - wg.y;
            float bz = sG[bt + 3 * j + 2] - wg.z;
            h00 += ax * bx; h01 += ax * by; h02 += ax * bz;
            h10 += ay * bx; h11 += ay * by; h12 += ay * bz;
            h20 += az * bx; h21 += az * by; h22 += az * bz;
        }

        // ---- Horn 4x4 matrix; max eigenvector = quaternion of Kabsch R ----
        float A00 = h00 + h11 + h22;
        float A01 = h12 - h21;
        float A02 = h20 - h02;
        float A03 = h01 - h10;
        float A11 = h00 - h11 - h22;
        float A12 = h01 + h10;
        float A13 = h02 + h20;
        float A22 = -h00 + h11 - h22;
        float A23 = h12 + h21;
        float A33 = -h00 - h11 + h22;

        float V00 = 1.f, V01 = 0.f, V02 = 0.f, V03 = 0.f;
        float V10 = 0.f, V11 = 1.f, V12 = 0.f, V13 = 0.f;
        float V20 = 0.f, V21 = 0.f, V22 = 1.f, V23 = 0.f;
        float V30 = 0.f, V31 = 0.f, V32 = 0.f, V33 = 1.f;

        // Brent-Luk paired ordering: 3 stages of disjoint pairs per sweep.
        // 3 sweeps: convergence saturated at sweep 4 (R3 vs R6 identical rel_err),
        // so sweep-3 residual is already small; quadratic convergence regime.
        #pragma unroll
        for (int sweep = 0; sweep < 3; ++sweep) {
            // stage 1: (0,1) || (2,3)
            JROT(A00, A11, A01, A02, A12, A03, A13, V00, V01, V10, V11, V20, V21, V30, V31);
            JROT(A22, A33, A23, A02, A03, A12, A13, V02, V03, V12, V13, V22, V23, V32, V33);
            // stage 2: (0,2) || (1,3)
            JROT(A00, A22, A02, A01, A12, A03, A23, V00, V02, V10, V12, V20, V22, V30, V32);
            JROT(A11, A33, A13, A01, A03, A12, A23, V01, V03, V11, V13, V21, V23, V31, V33);
            // stage 3: (0,3) || (1,2)
            JROT(A00, A33, A03, A01, A13, A02, A23, V00, V03, V10, V13, V20, V23, V30, V33);
            JROT(A11, A22, A12, A01, A02, A13, A23, V01, V02, V11, V12, V21, V22, V31, V32);
        }

        float qw = V00, qx = V10, qy = V20, qz = V30, bd = A00;
        if (A11 > bd) { bd = A11; qw = V01; qx = V11; qy = V21; qz = V31; }
        if (A22 > bd) { bd = A22; qw = V02; qx = V12; qy = V22; qz = V32; }
        if (A33 > bd) { bd = A33; qw = V03; qx = V13; qy = V23; qz = V33; }
        float qn = rsqrtf(qw * qw + qx * qx + qy * qy + qz * qz);
        qw *= qn; qx *= qn; qy *= qn; qz *= qn;

        const float r00 = 1.f - 2.f * (qy * qy + qz * qz);
        const float r01 = 2.f * (qx * qy - qw * qz);
        const float r02 = 2.f * (qx * qz + qw * qy);
        const float r10 = 2.f * (qx * qy + qw * qz);
        const float r11 = 1.f - 2.f * (qx * qx + qz * qz);
        const float r12 = 2.f * (qy * qz - qw * qx);
        const float r20 = 2.f * (qx * qz - qw * qy);
        const float r21 = 2.f * (qy * qz + qw * qx);
        const float r22 = 1.f - 2.f * (qx * qx + qy * qy);

        // output joint 0 = wrist of joint_gt
        sT[bt + 0] = wg.x; sT[bt + 1] = wg.y; sT[bt + 2] = wg.z;

        // ---- per-finger chain. Bone rotation identities used:
        //   (1) R(n0->n1) maps v0 exactly to |v0|*n1  -> direct child needs no rotApply
        //   (2) with a = n0 x n1 (unnormalized), R w = w + a x w + (a x (a x w))/(1+c)
        //       since (1-c)/s^2 = 1/(1+c). No axis normalization needed.
        const int tipIdx[5] = {17, 18, 20, 19, 16};
        #pragma unroll
        for (int f = 0; f < 5; ++f) {
            const int a0 = 3 * f + 1;
            const int jidx[4] = {a0, a0 + 1, a0 + 2, tipIdx[f]};
            V3 P[4], G[3];
            #pragma unroll
            for (int k = 0; k < 4; ++k) {
                const int j = jidx[k];
                float tx = sT[bt + 3 * j + 0] - wt.x;
                float ty = sT[bt + 3 * j + 1] - wt.y;
                float tz = sT[bt + 3 * j + 2] - wt.z;
                P[k] = mkv3(r00 * tx + r01 * ty + r02 * tz,
                            r10 * tx + r11 * ty + r12 * tz,
                            r20 * tx + r21 * ty + r22 * tz);
            }
            #pragma unroll
            for (int k = 0; k < 3; ++k) {
                const int j = jidx[k + 1];
                G[k] = mkv3(sG[bt + 3 * j + 0] - wg.x,
                            sG[bt + 3 * j + 1] - wg.y,
                            sG[bt + 3 * j + 2] - wg.z);
            }
            {   // bone 1: pivot P0; direct child P1; rotate P2, P3
                V3 v0 = sub3(P[1], P[0]);
                V3 v1 = sub3(G[0], P[0]);
                float d0 = dot3(v0, v0), d1 = dot3(v1, v1);
                float i0 = rsqrtf(fmaxf(d0, 1e-30f));
                float i1 = rsqrtf(fmaxf(d1, 1e-30f));
                V3 n0 = scl3(v0, i0), n1 = scl3(v1, i1);
                float c = dot3(n0, n1);
                V3 ax = cross3(n0, n1);
                float fct = __fdividef(1.0f, fmaxf(1.0f + c, 1e-12f));
                P[1] = add3(P[0], scl3(n1, d0 * i0));
                V3 w2 = sub3(P[2], P[0]);
                V3 aw2 = cross3(ax, w2); V3 aaw2 = cross3(ax, aw2);
                P[2] = add3(P[0], add3(w2, add3(aw2, scl3(aaw2, fct))));
                V3 w3 = sub3(P[3], P[0]);
                V3 aw3 = cross3(ax, w3); V3 aaw3 = cross3(ax, aw3);
                P[3] = add3(P[0], add3(w3, add3(aw3, scl3(aaw3, fct))));
            }
            {   // bone 2: pivot P1; direct child P2; rotate P3
                V3 v0 = sub3(P[2], P[1]);
                V3 v1 = sub3(G[1], P[1]);
                float d0 = dot3(v0, v0), d1 = dot3(v1, v1);
                float i0 = rsqrtf(fmaxf(d0, 1e-30f));
                float i1 = rsqrtf(fmaxf(d1, 1e-30f));
                V3 n0 = scl3(v0, i0), n1 = scl3(v1, i1);
                float c = dot3(n0, n1);
                V3 ax = cross3(n0, n1);
                float fct = __fdividef(1.0f, fmaxf(1.0f + c, 1e-12f));
                P[2] = add3(P[1], scl3(n1, d0 * i0));
                V3 w3 = sub3(P[3], P[1]);
                V3 aw3 = cross3(ax, w3); V3 aaw3 = cross3(ax, aw3);
                P[3] = add3(P[1], add3(w3, add3(aw3, scl3(aaw3, fct))));
            }
            {   // bone 3: pivot P2; direct child P3 only -> pure length transfer
                V3 v0 = sub3(P[3], P[2]);
                V3 v1 = sub3(G[2], P[2]);
                float d0 = dot3(v0, v0), d1 = dot3(v1, v1);
                float i0 = rsqrtf(fmaxf(d0, 1e-30f));
                float i1 = rsqrtf(fmaxf(d1, 1e-30f));
                P[3] = add3(P[2], scl3(v1, d0 * i0 * i1));
            }
            #pragma unroll
            for (int k = 0; k < 4; ++k) {
                const int j = jidx[k];
                sT[bt + 3 * j + 0] = P[k].x + wg.x;
                sT[bt + 3 * j + 1] = P[k].y + wg.y;
                sT[bt + 3 * j + 2] = P[k].z + wg.z;
            }
        }
    }
    __syncthreads();

    // ---- coalesced store: smem -> gmem ----
    if (full) {
        float4* o4 = reinterpret_cast<float4*>(out + base);
        const float4* sT4 = reinterpret_cast<const float4*>(sT);
        #pragma unroll 4
        for (int k = tid; k < TILE / 4; k += NBLK) o4[k] = sT4[k];
    } else {
        for (int k = tid; k < TILE; k += NBLK) {
            long long gi = base + k;
            if (gi < nF) out[gi] = sT[k];
        }
    }
}

extern "C" void kernel_launch(void* const* d_in, const int* in_sizes, int n_in,
                              void* d_out, int out_size) {
    const float* jgt = (const float*)d_in[0];   // joint_gt [N,21,3]
    const float* tpl = (const float*)d_in[1];   // tempJ    [N,21,3]
    float* out = (float*)d_out;                 // [N,21,3] float32
    (void)n_in; (void)out_size;

    static bool attr_set = false;               // idempotent attribute config
    if (!attr_set) {
        cudaFuncSetAttribute(kin_kernel, cudaFuncAttributeMaxDynamicSharedMemorySize, SMEM_BYTES);
        attr_set = true;
    }

    const int n = in_sizes[0] / FPT;
    const int blocks = (n + NBLK - 1) / NBLK;
    kin_kernel<<<blocks, NBLK, SMEM_BYTES>>>(jgt, tpl, out, n);
}

// round 16
// speedup vs baseline: 1.3930x; 1.0276x over previous
#include <cuda_runtime.h>

#define NBLK 128
#define NJ   21
#define FPT  63                 // floats per sample (21 joints x 3)
#define TILE (NBLK * FPT)       // 8064 floats per array per block
#define SMEM_BYTES (2 * TILE * (int)sizeof(float))   // 64512 B

struct V3 { float x, y, z; };

__device__ __forceinline__ V3 mkv3(float x, float y, float z) { V3 r; r.x = x; r.y = y; r.z = z; return r; }
__device__ __forceinline__ V3 sub3(V3 a, V3 b) { return mkv3(a.x - b.x, a.y - b.y, a.z - b.z); }
__device__ __forceinline__ V3 add3(V3 a, V3 b) { return mkv3(a.x + b.x, a.y + b.y, a.z + b.z); }
__device__ __forceinline__ V3 scl3(V3 a, float s) { return mkv3(a.x * s, a.y * s, a.z * s); }
__device__ __forceinline__ float dot3(V3 a, V3 b) { return a.x * b.x + a.y * b.y + a.z * b.z; }
__device__ __forceinline__ V3 cross3(V3 a, V3 b) {
    return mkv3(a.y * b.z - a.z * b.y, a.z * b.x - a.x * b.z, a.x * b.y - a.y * b.x);
}

// ---- packed f32x2 helpers (Blackwell sm_103a: mul/fma.rn.f32x2) ----
__device__ __forceinline__ unsigned long long pk2f(float lo, float hi) {
    unsigned long long r;
    asm("mov.b64 %0, {%1, %2};" : "=l"(r) : "r"(__float_as_uint(lo)), "r"(__float_as_uint(hi)));
    return r;
}
__device__ __forceinline__ unsigned long long mul2(unsigned long long a, unsigned long long b) {
    unsigned long long r;
    asm("mul.rn.f32x2 %0, %1, %2;" : "=l"(r) : "l"(a), "l"(b));
    return r;
}
__device__ __forceinline__ unsigned long long fma2(unsigned long long a, unsigned long long b, unsigned long long c) {
    unsigned long long r;
    asm("fma.rn.f32x2 %0, %1, %2, %3;" : "=l"(r) : "l"(a), "l"(b), "l"(c));
    return r;
}
__device__ __forceinline__ void upk2(unsigned long long v, float& lo, float& hi) {
    unsigned int a, b;
    asm("mov.b64 {%0, %1}, %2;" : "=r"(a), "=r"(b) : "l"(v));
    lo = __uint_as_float(a); hi = __uint_as_float(b);
}

// Branchless division-free exact Jacobi rotation (pair P,Q). V columns packed
// as row-pairs (vaX = rows 0,1 of column X; vbX = rows 2,3).
// Fully self-contained macro: every varying identifier is a formal parameter.
#define JROTP(app, aqq, apq, arp1, arq1, arp2, arq2, vaP, vaQ, vbP, vbQ)                    \
do {                                                                                        \
    float _apq = apq;                                                                       \
    float _t2  = 2.0f * _apq;                                                               \
    float _d   = (aqq) - (app);                                                             \
    float _invr = rsqrtf(fmaxf(_t2 * _t2 + _d * _d, 1e-38f));                               \
    float _co  = fabsf(_d) * _invr;                                                         \
    float _c2v = 0.5f * (1.0f + _co);                                                       \
    float _ir2 = rsqrtf(_c2v);                                                              \
    float _cc  = _c2v * _ir2;                                                               \
    float _sg  = (_d >= 0.0f) ? 0.5f : -0.5f;                                               \
    float _ss  = _sg * _t2 * _invr * _ir2;                                                  \
    float _tt  = _ss * _ir2;                                                                \
    app = (app) - _tt * _apq;                                                               \
    aqq = (aqq) + _tt * _apq;                                                               \
    apq = 0.0f;                                                                             \
    float _t1x, _t2x;                                                                       \
    _t1x = arp1; _t2x = arq1; arp1 = _cc*_t1x - _ss*_t2x; arq1 = _ss*_t1x + _cc*_t2x;       \
    _t1x = arp2; _t2x = arq2; arp2 = _cc*_t1x - _ss*_t2x; arq2 = _ss*_t1x + _cc*_t2x;       \
    unsigned long long _cc2 = pk2f(_cc, _cc);                                               \
    unsigned long long _ss2 = pk2f(_ss, _ss);                                               \
    unsigned long long _sn2 = pk2f(-_ss, -_ss);                                             \
    unsigned long long _tp;                                                                 \
    _tp = vaP; vaP = fma2(_cc2, _tp, mul2(_sn2, vaQ)); vaQ = fma2(_cc2, vaQ, mul2(_ss2, _tp)); \
    _tp = vbP; vbP = fma2(_cc2, _tp, mul2(_sn2, vbQ)); vbQ = fma2(_cc2, vbQ, mul2(_ss2, _tp)); \
} while (0)

// Final-stage variant: A off-diagonal updates are dead (never read after last
// stage); keep diagonal updates (used by column pick) and V updates.
#define JROTP_LAST(app, aqq, apq, vaP, vaQ, vbP, vbQ)                                       \
do {                                                                                        \
    float _apq = apq;                                                                       \
    float _t2  = 2.0f * _apq;                                                               \
    float _d   = (aqq) - (app);                                                             \
    float _invr = rsqrtf(fmaxf(_t2 * _t2 + _d * _d, 1e-38f));                               \
    float _co  = fabsf(_d) * _invr;                                                         \
    float _c2v = 0.5f * (1.0f + _co);                                                       \
    float _ir2 = rsqrtf(_c2v);                                                              \
    float _cc  = _c2v * _ir2;                                                               \
    float _sg  = (_d >= 0.0f) ? 0.5f : -0.5f;                                               \
    float _ss  = _sg * _t2 * _invr * _ir2;                                                  \
    float _tt  = _ss * _ir2;                                                                \
    app = (app) - _tt * _apq;                                                               \
    aqq = (aqq) + _tt * _apq;                                                               \
    unsigned long long _cc2 = pk2f(_cc, _cc);                                               \
    unsigned long long _ss2 = pk2f(_ss, _ss);                                               \
    unsigned long long _sn2 = pk2f(-_ss, -_ss);                                             \
    unsigned long long _tp;                                                                 \
    _tp = vaP; vaP = fma2(_cc2, _tp, mul2(_sn2, vaQ)); vaQ = fma2(_cc2, vaQ, mul2(_ss2, _tp)); \
    _tp = vbP; vbP = fma2(_cc2, _tp, mul2(_sn2, vbQ)); vbQ = fma2(_cc2, vbQ, mul2(_ss2, _tp)); \
} while (0)

__global__ void __launch_bounds__(NBLK, 3)
kin_kernel(const float* __restrict__ jgt, const float* __restrict__ tpl,
           float* __restrict__ out, int n)
{
    extern __shared__ float smem_dyn[];
    float* sG = smem_dyn;          // joint_gt tile
    float* sT = smem_dyn + TILE;   // tempJ tile; reused as output tile

    const int tid = threadIdx.x;
    const long long base = (long long)blockIdx.x * TILE;
    const long long nF = (long long)n * FPT;
    const bool full = (base + TILE) <= nF;

    // ---- coalesced staging: gmem -> smem ----
    if (full) {
        const float4* g4 = reinterpret_cast<const float4*>(jgt + base);
        const float4* t4 = reinterpret_cast<const float4*>(tpl + base);
        float4* sG4 = reinterpret_cast<float4*>(sG);
        float4* sT4 = reinterpret_cast<float4*>(sT);
        #pragma unroll 4
        for (int k = tid; k < TILE / 4; k += NBLK) { sG4[k] = g4[k]; sT4[k] = t4[k]; }
    } else {
        for (int k = tid; k < TILE; k += NBLK) {
            long long gi = base + k;
            if (gi < nF) { sG[k] = jgt[gi]; sT[k] = tpl[gi]; }
        }
    }
    __syncthreads();

    const int samp = blockIdx.x * NBLK + tid;
    if (samp < n) {
        const int bt = tid * FPT;
        const V3 wg = mkv3(sG[bt + 0], sG[bt + 1], sG[bt + 2]);  // joint_gt wrist
        const V3 wt = mkv3(sT[bt + 0], sT[bt + 1], sT[bt + 2]);  // tempJ wrist

        // ---- H = sum_j tJ0_j * jg_j^T (j=0 term is exactly zero) ----
        float h00 = 0.f, h01 = 0.f, h02 = 0.f;
        float h10 = 0.f, h11 = 0.f, h12 = 0.f;
        float h20 = 0.f, h21 = 0.f, h22 = 0.f;
        #pragma unroll
        for (int j = 1; j < NJ; ++j) {
            float ax = sT[bt + 3 * j + 0] - wt.x;
            float ay = sT[bt + 3 * j + 1] - wt.y;
            float az = sT[bt + 3 * j + 2] - wt.z;
            float bx = sG[bt + 3 * j + 0] - wg.x;
            float by = sG[bt + 3 * j + 1] - wg.y;
            float bz = sG[bt + 3 * j + 2] - wg.z;
            h00 += ax * bx; h01 += ax * by; h02 += ax * bz;
            h10 += ay * bx; h11 += ay * by; h12 += ay * bz;
            h20 += az * bx; h21 += az * by; h22 += az * bz;
        }

        // ---- Horn 4x4 matrix; max eigenvector = quaternion of Kabsch R ----
        float A00 = h00 + h11 + h22;
        float A01 = h12 - h21;
        float A02 = h20 - h02;
        float A03 = h01 - h10;
        float A11 = h00 - h11 - h22;
        float A12 = h01 + h10;
        float A13 = h02 + h20;
        float A22 = -h00 + h11 - h22;
        float A23 = h12 + h21;
        float A33 = -h00 - h11 + h22;

        // V as packed row-pairs: VaC = (V0C,V1C), VbC = (V2C,V3C); init = identity
        unsigned long long Va0 = pk2f(1.f, 0.f), Va1 = pk2f(0.f, 1.f);
        unsigned long long Va2 = pk2f(0.f, 0.f), Va3 = pk2f(0.f, 0.f);
        unsigned long long Vb0 = pk2f(0.f, 0.f), Vb1 = pk2f(0.f, 0.f);
        unsigned long long Vb2 = pk2f(1.f, 0.f), Vb3 = pk2f(0.f, 1.f);

        // Brent-Luk paired ordering, 3 sweeps; final stage drops dead A updates.
        #pragma unroll
        for (int sweep = 0; sweep < 2; ++sweep) {
            JROTP(A00, A11, A01, A02, A12, A03, A13, Va0, Va1, Vb0, Vb1);
            JROTP(A22, A33, A23, A02, A03, A12, A13, Va2, Va3, Vb2, Vb3);
            JROTP(A00, A22, A02, A01, A12, A03, A23, Va0, Va2, Vb0, Vb2);
            JROTP(A11, A33, A13, A01, A03, A12, A23, Va1, Va3, Vb1, Vb3);
            JROTP(A00, A33, A03, A01, A13, A02, A23, Va0, Va3, Vb0, Vb3);
            JROTP(A11, A22, A12, A01, A02, A13, A23, Va1, Va2, Vb1, Vb2);
        }
        JROTP(A00, A11, A01, A02, A12, A03, A13, Va0, Va1, Vb0, Vb1);
        JROTP(A22, A33, A23, A02, A03, A12, A13, Va2, Va3, Vb2, Vb3);
        JROTP(A00, A22, A02, A01, A12, A03, A23, Va0, Va2, Vb0, Vb2);
        JROTP(A11, A33, A13, A01, A03, A12, A23, Va1, Va3, Vb1, Vb3);
        JROTP_LAST(A00, A33, A03, Va0, Va3, Vb0, Vb3);
        JROTP_LAST(A11, A22, A12, Va1, Va2, Vb1, Vb2);

        // pick column with largest diagonal (eigenvalue estimate)
        unsigned long long sa = Va0, sb = Vb0; float bd = A00;
        if (A11 > bd) { bd = A11; sa = Va1; sb = Vb1; }
        if (A22 > bd) { bd = A22; sa = Va2; sb = Vb2; }
        if (A33 > bd) { bd = A33; sa = Va3; sb = Vb3; }
        float qw, qx, qy, qz;
        upk2(sa, qw, qx);
        upk2(sb, qy, qz);
        float qn = rsqrtf(qw * qw + qx * qx + qy * qy + qz * qz);
        qw *= qn; qx *= qn; qy *= qn; qz *= qn;

        const float r00 = 1.f - 2.f * (qy * qy + qz * qz);
        const float r01 = 2.f * (qx * qy - qw * qz);
        const float r02 = 2.f * (qx * qz + qw * qy);
        const float r10 = 2.f * (qx * qy + qw * qz);
        const float r11 = 1.f - 2.f * (qx * qx + qz * qz);
        const float r12 = 2.f * (qy * qz - qw * qx);
        const float r20 = 2.f * (qx * qz - qw * qy);
        const float r21 = 2.f * (qy * qz + qw * qx);
        const float r22 = 1.f - 2.f * (qx * qx + qy * qy);

        // output joint 0 = wrist of joint_gt
        sT[bt + 0] = wg.x; sT[bt + 1] = wg.y; sT[bt + 2] = wg.z;

        // ---- per-finger chain. Bone rotation identities used:
        //   (1) R(n0->n1) maps v0 exactly to |v0|*n1  -> direct child needs no rotApply
        //   (2) with a = n0 x n1 (unnormalized), R w = w + a x w + (a x (a x w))/(1+c)
        //       since (1-c)/s^2 = 1/(1+c). No axis normalization needed.
        const int tipIdx[5] = {17, 18, 20, 19, 16};
        #pragma unroll
        for (int f = 0; f < 5; ++f) {
            const int a0 = 3 * f + 1;
            const int jidx[4] = {a0, a0 + 1, a0 + 2, tipIdx[f]};
            V3 P[4], G[3];
            #pragma unroll
            for (int k = 0; k < 4; ++k) {
                const int j = jidx[k];
                float tx = sT[bt + 3 * j + 0] - wt.x;
                float ty = sT[bt + 3 * j + 1] - wt.y;
                float tz = sT[bt + 3 * j + 2] - wt.z;
                P[k] = mkv3(r00 * tx + r01 * ty + r02 * tz,
                            r10 * tx + r11 * ty + r12 * tz,
                            r20 * tx + r21 * ty + r22 * tz);
            }
            #pragma unroll
            for (int k = 0; k < 3; ++k) {
                const int j = jidx[k + 1];
                G[k] = mkv3(sG[bt + 3 * j + 0] - wg.x,
                            sG[bt + 3 * j + 1] - wg.y,
                            sG[bt + 3 * j + 2] - wg.z);
            }
            {   // bone 1: pivot P0; direct child P1; rotate P2, P3
                V3 v0 = sub3(P[1], P[0]);
                V3 v1 = sub3(G[0], P[0]);
                float d0 = dot3(v0, v0), d1 = dot3(v1, v1);
                float i0 = rsqrtf(fmaxf(d0, 1e-30f));
                float i1 = rsqrtf(fmaxf(d1, 1e-30f));
                V3 n0 = scl3(v0, i0), n1 = scl3(v1, i1);
                float c = dot3(n0, n1);
                V3 ax = cross3(n0, n1);
                float fct = __fdividef(1.0f, fmaxf(1.0f + c, 1e-12f));
                P[1] = add3(P[0], scl3(n1, d0 * i0));
                V3 w2 = sub3(P[2], P[0]);
                V3 aw2 = cross3(ax, w2); V3 aaw2 = cross3(ax, aw2);
                P[2] = add3(P[0], add3(w2, add3(aw2, scl3(aaw2, fct))));
                V3 w3 = sub3(P[3], P[0]);
                V3 aw3 = cross3(ax, w3); V3 aaw3 = cross3(ax, aw3);
                P[3] = add3(P[0], add3(w3, add3(aw3, scl3(aaw3, fct))));
            }
            {   // bone 2: pivot P1; direct child P2; rotate P3
                V3 v0 = sub3(P[2], P[1]);
                V3 v1 = sub3(G[1], P[1]);
                float d0 = dot3(v0, v0), d1 = dot3(v1, v1);
                float i0 = rsqrtf(fmaxf(d0, 1e-30f));
                float i1 = rsqrtf(fmaxf(d1, 1e-30f));
                V3 n0 = scl3(v0, i0), n1 = scl3(v1, i1);
                float c = dot3(n0, n1);
                V3 ax = cross3(n0, n1);
                float fct = __fdividef(1.0f, fmaxf(1.0f + c, 1e-12f));
                P[2] = add3(P[1], scl3(n1, d0 * i0));
                V3 w3 = sub3(P[3], P[1]);
                V3 aw3 = cross3(ax, w3); V3 aaw3 = cross3(ax, aw3);
                P[3] = add3(P[1], add3(w3, add3(aw3, scl3(aaw3, fct))));
            }
            {   // bone 3: pivot P2; direct child P3 only -> pure length transfer
                V3 v0 = sub3(P[3], P[2]);
                V3 v1 = sub3(G[2], P[2]);
                float d0 = dot3(v0, v0), d1 = dot3(v1, v1);
                float i0 = rsqrtf(fmaxf(d0, 1e-30f));
                float i1 = rsqrtf(fmaxf(d1, 1e-30f));
                P[3] = add3(P[2], scl3(v1, d0 * i0 * i1));
            }
            #pragma unroll
            for (int k = 0; k < 4; ++k) {
                const int j = jidx[k];
                sT[bt + 3 * j + 0] = P[k].x + wg.x;
                sT[bt + 3 * j + 1] = P[k].y + wg.y;
                sT[bt + 3 * j + 2] = P[k].z + wg.z;
            }
        }
    }
    __syncthreads();

    // ---- coalesced store: smem -> gmem ----
    if (full) {
        float4* o4 = reinterpret_cast<float4*>(out + base);
        const float4* sT4 = reinterpret_cast<const float4*>(sT);
        #pragma unroll 4
        for (int k = tid; k < TILE / 4; k += NBLK) o4[k] = sT4[k];
    } else {
        for (int k = tid; k < TILE; k += NBLK) {
            long long gi = base + k;
            if (gi < nF) out[gi] = sT[k];
        }
    }
}

extern "C" void kernel_launch(void* const* d_in, const int* in_sizes, int n_in,
                              void* d_out, int out_size) {
    const float* jgt = (const float*)d_in[0];   // joint_gt [N,21,3]
    const float* tpl = (const float*)d_in[1];   // tempJ    [N,21,3]
    float* out = (float*)d_out;                 // [N,21,3] float32
    (void)n_in; (void)out_size;

    static bool attr_set = false;               // idempotent attribute config
    if (!attr_set) {
        cudaFuncSetAttribute(kin_kernel, cudaFuncAttributeMaxDynamicSharedMemorySize, SMEM_BYTES);
        attr_set = true;
    }

    const int n = in_sizes[0] / FPT;
    const int blocks = (n + NBLK - 1) / NBLK;
    kin_kernel<<<blocks, NBLK, SMEM_BYTES>>>(jgt, tpl, out, n);
}